// round 1
// baseline (speedup 1.0000x reference)
#include <cuda_runtime.h>
#include <float.h>

// Shapes are fixed by the problem: D=768, N=128, B=512, max_bag=32 (actual sizes 8..24).
#define D_DIM   768
#define NREL    128
#define MAXM    32
#define BK      32      // W d-tile
#define CH      192     // rep d-chunk held in smem
#define WPITCH  36      // 32 + 4 pad: conflict-free column access, 16B aligned
#define APITCH  132     // 128 + 4 pad
#define NTHREADS 256

struct Smem {
    float repS[MAXM][CH];      // 24576 B
    float wS[NREL][WPITCH];    // 18432 B
    float attS[MAXM][APITCH];  // 16896 B
    float biasS[NREL];         //   512 B
};                             // total 60416 B

__global__ __launch_bounds__(NTHREADS, 2)
void bag_attn_kernel(const float* __restrict__ rep,
                     const float* __restrict__ W,
                     const float* __restrict__ bias,
                     const int*   __restrict__ scope,
                     float*       __restrict__ out)
{
    extern __shared__ char smraw[];
    Smem& s = *reinterpret_cast<Smem*>(smraw);
    const int b    = blockIdx.x;
    const int t    = threadIdx.x;
    const int lane = t & 31;
    const int warp = t >> 5;

    const int start = scope[2 * b];
    int m = scope[2 * b + 1] - start;
    if (m > MAXM) m = MAXM;          // reference masks pos >= max_bag too

    if (t < NREL) s.biasS[t] = bias[t];

    // ---------------- Phase A: att[j,k] = rep[start+j] . W[k] ----------------
    // thread layout: k = t & 127, jj = t >> 7; thread owns j = jj, jj+2, jj+4, ...
    const int k  = t & (NREL - 1);
    const int jj = t >> 7;
    const int nj = (m > jj) ? ((m - jj + 1) >> 1) : 0;

    float acc[MAXM / 2];
#pragma unroll
    for (int i = 0; i < MAXM / 2; ++i) acc[i] = 0.f;

    for (int c = 0; c < D_DIM; c += CH) {
        __syncthreads();  // previous chunk's compute done before repS overwrite
        // load rep chunk: m * CH floats, coalesced vec4
        const int tot4 = m * (CH / 4);
        for (int idx = t; idx < tot4; idx += NTHREADS) {
            const int j   = idx / (CH / 4);
            const int col = (idx - j * (CH / 4)) * 4;
            const float4 v = *reinterpret_cast<const float4*>(
                rep + (size_t)(start + j) * D_DIM + c + col);
            *reinterpret_cast<float4*>(&s.repS[j][col]) = v;
        }
        for (int tb = 0; tb < CH; tb += BK) {
            __syncthreads();  // repS ready / previous wS consumed
            // load W tile [128][32]: 1024 float4, 4 per thread, coalesced
#pragma unroll
            for (int r = 0; r < 4; ++r) {
                const int idx = t + r * NTHREADS;
                const int row = idx >> 3;
                const int col = (idx & 7) * 4;
                const float4 v = *reinterpret_cast<const float4*>(
                    W + (size_t)row * D_DIM + c + tb + col);
                *reinterpret_cast<float4*>(&s.wS[row][col]) = v;
            }
            __syncthreads();  // wS ready
#pragma unroll
            for (int d4 = 0; d4 < BK; d4 += 4) {
                const float4 w4 = *reinterpret_cast<const float4*>(&s.wS[k][d4]);
#pragma unroll
                for (int i = 0; i < MAXM / 2; ++i) {
                    if (i < nj) {
                        const float4 r4 = *reinterpret_cast<const float4*>(
                            &s.repS[jj + 2 * i][tb + d4]);
                        acc[i] = fmaf(r4.x, w4.x, acc[i]);
                        acc[i] = fmaf(r4.y, w4.y, acc[i]);
                        acc[i] = fmaf(r4.z, w4.z, acc[i]);
                        acc[i] = fmaf(r4.w, w4.w, acc[i]);
                    }
                }
            }
        }
    }

#pragma unroll
    for (int i = 0; i < MAXM / 2; ++i) {
        if (i < nj) s.attS[jj + 2 * i][k] = acc[i];
    }
    __syncthreads();

    // ---------------- Phase B: softmax_j, full = sm @ att + bias, softmax_k diag ----
    // warp handles 16 consecutive n; within a warp, lane = j for the column softmax,
    // then lane owns k in [4*lane, 4*lane+4) for the row pass.
    const int nbase = warp << 4;
    for (int ii = 0; ii < 16; ++ii) {
        const int n = nbase + ii;

        // softmax over bag members j (lane = j), invalid lanes -> weight 0
        float a = (lane < m) ? s.attS[lane][n] : -FLT_MAX;
        float mx = a;
#pragma unroll
        for (int o = 16; o; o >>= 1) mx = fmaxf(mx, __shfl_xor_sync(0xffffffffu, mx, o));
        float w = (lane < m) ? __expf(a - mx) : 0.f;
        float ssum = w;
#pragma unroll
        for (int o = 16; o; o >>= 1) ssum += __shfl_xor_sync(0xffffffffu, ssum, o);
        w /= ssum;                       // sm[n, lane]

        // full[n, k] for this lane's 4 k's
        float f0 = 0.f, f1 = 0.f, f2 = 0.f, f3 = 0.f;
        for (int j = 0; j < m; ++j) {
            const float wj = __shfl_sync(0xffffffffu, w, j);
            const float4 a4 = *reinterpret_cast<const float4*>(&s.attS[j][lane << 2]);
            f0 = fmaf(wj, a4.x, f0);
            f1 = fmaf(wj, a4.y, f1);
            f2 = fmaf(wj, a4.z, f2);
            f3 = fmaf(wj, a4.w, f3);
        }
        const float4 b4 = *reinterpret_cast<const float4*>(&s.biasS[lane << 2]);
        f0 += b4.x; f1 += b4.y; f2 += b4.z; f3 += b4.w;

        // row softmax over k = 0..127, output only diagonal element k == n
        float lm = fmaxf(fmaxf(f0, f1), fmaxf(f2, f3));
#pragma unroll
        for (int o = 16; o; o >>= 1) lm = fmaxf(lm, __shfl_xor_sync(0xffffffffu, lm, o));
        const float e0 = __expf(f0 - lm);
        const float e1 = __expf(f1 - lm);
        const float e2 = __expf(f2 - lm);
        const float e3 = __expf(f3 - lm);
        float es = e0 + e1 + e2 + e3;
#pragma unroll
        for (int o = 16; o; o >>= 1) es += __shfl_xor_sync(0xffffffffu, es, o);
        if ((n >> 2) == lane) {
            const int r = n & 3;
            const float ed = (r == 0) ? e0 : (r == 1) ? e1 : (r == 2) ? e2 : e3;
            out[(size_t)b * NREL + n] = ed / es;
        }
    }
}

extern "C" void kernel_launch(void* const* d_in, const int* in_sizes, int n_in,
                              void* d_out, int out_size)
{
    (void)n_in; (void)out_size;
    const float* rep   = (const float*)d_in[0];
    const float* W     = (const float*)d_in[1];
    const float* bias  = (const float*)d_in[2];
    const int*   scope = (const int*)d_in[3];
    float* out = (float*)d_out;

    const int B = in_sizes[3] / 2;   // scope has B*2 ints
    const int smem = (int)sizeof(Smem);
    cudaFuncSetAttribute(bag_attn_kernel,
                         cudaFuncAttributeMaxDynamicSharedMemorySize, smem);
    bag_attn_kernel<<<B, NTHREADS, smem>>>(rep, W, bias, scope, out);
}

// round 2
// speedup vs baseline: 1.6954x; 1.6954x over previous
#include <cuda_runtime.h>
#include <float.h>

#define D_DIM   768
#define NREL    128
#define MAXM    32
#define NTA     256       // threads, phase A
#define NTB     256       // threads, phase B
#define BM      32
#define BK      32
#define AP      35        // As pitch: scalar STS conflict-free (12c'+m covers 32 banks)
#define BP      33        // Bs pitch: LDS bank = tnc+kk (conflict-free)

__device__ float g_att[16384 * NREL];   // 8 MB scratch, L2-resident

// ---------------- Phase A: att = rep @ W^T  (M=nsum, N=128, K=768) ----------------
__global__ __launch_bounds__(NTA, 3)
void gemm_att_kernel(const float* __restrict__ rep,
                     const float* __restrict__ W,
                     int nsum)
{
    __shared__ float As[BK][AP];      // [kk][m]
    __shared__ float Bs[NREL][BP];    // [n][kk]

    const int t   = threadIdx.x;
    const int tnc = t & 31;           // n-col group
    const int tmr = t >> 5;           // m-row group (0..7)
    const int row0 = blockIdx.x * BM;

    // global-load lane mapping (coalesced 128B segments)
    const int lm = t >> 3;            // row in tile (0..31)
    const int lc = (t & 7) * 4;       // col (floats)

    const float* repp = rep + (size_t)min(row0 + lm, nsum - 1) * D_DIM + lc;

    float acc[4][4];
#pragma unroll
    for (int i = 0; i < 4; ++i)
#pragma unroll
        for (int j = 0; j < 4; ++j) acc[i][j] = 0.f;

    // prefetch tile 0 into registers
    float4 a4 = *reinterpret_cast<const float4*>(repp);
    float4 b4[4];
#pragma unroll
    for (int r = 0; r < 4; ++r) {
        const int g = t + NTA * r;
        b4[r] = *reinterpret_cast<const float4*>(W + (size_t)(g >> 3) * D_DIM + (g & 7) * 4);
    }

    for (int c = 0; c < D_DIM; c += BK) {
        __syncthreads();              // previous compute done before smem overwrite
        // store A transposed (conflict-free scalar STS, pitch 35)
        As[lc + 0][lm] = a4.x;
        As[lc + 1][lm] = a4.y;
        As[lc + 2][lm] = a4.z;
        As[lc + 3][lm] = a4.w;
        // store B natural [n][kk] (conflict-free scalar STS, pitch 33)
#pragma unroll
        for (int r = 0; r < 4; ++r) {
            const int g = t + NTA * r;
            const int n = g >> 3;
            const int cc = (g & 7) * 4;
            Bs[n][cc + 0] = b4[r].x;
            Bs[n][cc + 1] = b4[r].y;
            Bs[n][cc + 2] = b4[r].z;
            Bs[n][cc + 3] = b4[r].w;
        }
        __syncthreads();
        // prefetch next tile (hidden under compute)
        if (c + BK < D_DIM) {
            a4 = *reinterpret_cast<const float4*>(repp + c + BK);
#pragma unroll
            for (int r = 0; r < 4; ++r) {
                const int g = t + NTA * r;
                b4[r] = *reinterpret_cast<const float4*>(
                    W + (size_t)(g >> 3) * D_DIM + c + BK + (g & 7) * 4);
            }
        }
        // compute: 32 kk, 4x4 register tile
#pragma unroll
        for (int kk = 0; kk < BK; ++kk) {
            float a[4], b[4];
#pragma unroll
            for (int i = 0; i < 4; ++i) a[i] = As[kk][tmr * 4 + i];   // broadcast
#pragma unroll
            for (int j = 0; j < 4; ++j) b[j] = Bs[tnc + 32 * j][kk];  // conflict-free
#pragma unroll
            for (int i = 0; i < 4; ++i)
#pragma unroll
                for (int j = 0; j < 4; ++j)
                    acc[i][j] = fmaf(a[i], b[j], acc[i][j]);
        }
    }

#pragma unroll
    for (int i = 0; i < 4; ++i) {
        const int row = row0 + tmr * 4 + i;
        if (row < nsum) {
#pragma unroll
            for (int j = 0; j < 4; ++j)
                g_att[(size_t)row * NREL + tnc + 32 * j] = acc[i][j];
        }
    }
}

// ---------------- Phase B: per-bag softmax chain ----------------
__global__ __launch_bounds__(NTB, 4)
void bag_softmax_kernel(const float* __restrict__ bias,
                        const int*   __restrict__ scope,
                        float*       __restrict__ out,
                        int nsum)
{
    __shared__ float attS[MAXM][NREL + 4];
    __shared__ float biasS[NREL];

    const int b    = blockIdx.x;
    const int t    = threadIdx.x;
    const int lane = t & 31;
    const int warp = t >> 5;

    const int start = scope[2 * b];
    int m = scope[2 * b + 1] - start;
    if (m > MAXM) m = MAXM;

    if (t < NREL) biasS[t] = bias[t];

    // load att rows for this bag (L2-resident scratch), coalesced vec4
    const int tot4 = m * (NREL / 4);
    for (int idx = t; idx < tot4; idx += NTB) {
        const int j    = idx >> 5;
        const int col  = (idx & 31) * 4;
        const float4 v = *reinterpret_cast<const float4*>(
            &g_att[(size_t)(start + j) * NREL + col]);
        *reinterpret_cast<float4*>(&attS[j][col]) = v;
    }
    __syncthreads();

    // 8 warps x 16 n each
    const int nbase = warp << 4;
    for (int ii = 0; ii < 16; ++ii) {
        const int n = nbase + ii;

        // softmax over bag members j (lane = j)
        float a = (lane < m) ? attS[lane][n] : -FLT_MAX;
        float mx = a;
#pragma unroll
        for (int o = 16; o; o >>= 1) mx = fmaxf(mx, __shfl_xor_sync(0xffffffffu, mx, o));
        float w = (lane < m) ? __expf(a - mx) : 0.f;
        float ssum = w;
#pragma unroll
        for (int o = 16; o; o >>= 1) ssum += __shfl_xor_sync(0xffffffffu, ssum, o);
        w /= ssum;

        // full[n, k] for this lane's 4 k's: Sum_j sm[n,j] * att[j,k]
        float f0 = 0.f, f1 = 0.f, f2 = 0.f, f3 = 0.f;
        for (int j = 0; j < m; ++j) {
            const float wj = __shfl_sync(0xffffffffu, w, j);
            const float4 a4 = *reinterpret_cast<const float4*>(&attS[j][lane << 2]);
            f0 = fmaf(wj, a4.x, f0);
            f1 = fmaf(wj, a4.y, f1);
            f2 = fmaf(wj, a4.z, f2);
            f3 = fmaf(wj, a4.w, f3);
        }
        const float4 bb = *reinterpret_cast<const float4*>(&biasS[lane << 2]);
        f0 += bb.x; f1 += bb.y; f2 += bb.z; f3 += bb.w;

        // row softmax over k, emit diagonal k == n
        float lmx = fmaxf(fmaxf(f0, f1), fmaxf(f2, f3));
#pragma unroll
        for (int o = 16; o; o >>= 1) lmx = fmaxf(lmx, __shfl_xor_sync(0xffffffffu, lmx, o));
        const float e0 = __expf(f0 - lmx);
        const float e1 = __expf(f1 - lmx);
        const float e2 = __expf(f2 - lmx);
        const float e3 = __expf(f3 - lmx);
        float es = e0 + e1 + e2 + e3;
#pragma unroll
        for (int o = 16; o; o >>= 1) es += __shfl_xor_sync(0xffffffffu, es, o);
        if ((n >> 2) == lane) {
            const int r = n & 3;
            const float ed = (r == 0) ? e0 : (r == 1) ? e1 : (r == 2) ? e2 : e3;
            out[(size_t)b * NREL + n] = ed / es;
        }
    }
}

extern "C" void kernel_launch(void* const* d_in, const int* in_sizes, int n_in,
                              void* d_out, int out_size)
{
    (void)n_in; (void)out_size;
    const float* rep   = (const float*)d_in[0];
    const float* W     = (const float*)d_in[1];
    const float* bias  = (const float*)d_in[2];
    const int*   scope = (const int*)d_in[3];
    float* out = (float*)d_out;

    const int nsum = in_sizes[0] / D_DIM;
    const int B    = in_sizes[3] / 2;

    const int gridA = (nsum + BM - 1) / BM;
    gemm_att_kernel<<<gridA, NTA>>>(rep, W, nsum);
    bag_softmax_kernel<<<B, NTB>>>(bias, scope, out, nsum);
}

// round 4
// speedup vs baseline: 2.1669x; 1.2781x over previous
#include <cuda_runtime.h>
#include <float.h>

#define D_DIM   768
#define NREL    128
#define MAXM    32
#define BM      28        // 8200/28 = 293 tiles ~ 1.98/SM: balanced 2-wave
#define BK      32
#define NTA     224       // 7 warps; 4x4 thread tile covers 28x128
#define NTB     256
#define AP      28        // As pitch (floats): 112B rows, 16B aligned
#define BP      132       // Bs/attS/smS pitch: 528B rows, 16B aligned

__device__ float g_att[16384 * NREL];   // 8 MB scratch (L2-resident)

// ---------------- Phase A: att = rep @ W^T  (M=nsum, N=128, K=768) ----------------
__global__ __launch_bounds__(NTA, 2)
void gemm_att_kernel(const float* __restrict__ rep,
                     const float* __restrict__ W,
                     int nsum)
{
    __shared__ float As[BK][AP];     // [kk][m]
    __shared__ float Bs[BK][BP];     // [kk][n]

    const int t    = threadIdx.x;
    const int tnc  = t & 31;         // n-group: n = 4*tnc + j
    const int tmr  = t >> 5;         // m-group (0..6): m = 4*tmr + i
    const int row0 = blockIdx.x * BM;

    const int lm = t >> 3;           // 0..27
    const int lc = (t & 7) * 4;
    const float* repp = rep + (size_t)min(row0 + lm, nsum - 1) * D_DIM + lc;

    float acc[4][4];
#pragma unroll
    for (int i = 0; i < 4; ++i)
#pragma unroll
        for (int j = 0; j < 4; ++j) acc[i][j] = 0.f;

    // prefetch tile 0
    float4 a4 = *reinterpret_cast<const float4*>(repp);
    float4 b4[5];
#pragma unroll
    for (int r = 0; r < 5; ++r) {
        const int g = t + NTA * r;
        if (g < 1024)
            b4[r] = *reinterpret_cast<const float4*>(
                W + (size_t)(g >> 3) * D_DIM + (g & 7) * 4);
    }

    for (int c = 0; c < D_DIM; c += BK) {
        __syncthreads();
        // A transposed: As[kk][m]
        As[lc + 0][lm] = a4.x;
        As[lc + 1][lm] = a4.y;
        As[lc + 2][lm] = a4.z;
        As[lc + 3][lm] = a4.w;
        // B transposed: Bs[kk][n]
#pragma unroll
        for (int r = 0; r < 5; ++r) {
            const int g = t + NTA * r;
            if (g < 1024) {
                const int n  = g >> 3;
                const int kk = (g & 7) * 4;
                Bs[kk + 0][n] = b4[r].x;
                Bs[kk + 1][n] = b4[r].y;
                Bs[kk + 2][n] = b4[r].z;
                Bs[kk + 3][n] = b4[r].w;
            }
        }
        __syncthreads();
        // prefetch next tile under compute
        if (c + BK < D_DIM) {
            a4 = *reinterpret_cast<const float4*>(repp + c + BK);
#pragma unroll
            for (int r = 0; r < 5; ++r) {
                const int g = t + NTA * r;
                if (g < 1024)
                    b4[r] = *reinterpret_cast<const float4*>(
                        W + (size_t)(g >> 3) * D_DIM + c + BK + (g & 7) * 4);
            }
        }
#pragma unroll
        for (int kk = 0; kk < BK; ++kk) {
            const float4 av = *reinterpret_cast<const float4*>(&As[kk][tmr * 4]); // broadcast
            const float4 bv = *reinterpret_cast<const float4*>(&Bs[kk][tnc * 4]); // coalesced
            acc[0][0] = fmaf(av.x, bv.x, acc[0][0]);
            acc[0][1] = fmaf(av.x, bv.y, acc[0][1]);
            acc[0][2] = fmaf(av.x, bv.z, acc[0][2]);
            acc[0][3] = fmaf(av.x, bv.w, acc[0][3]);
            acc[1][0] = fmaf(av.y, bv.x, acc[1][0]);
            acc[1][1] = fmaf(av.y, bv.y, acc[1][1]);
            acc[1][2] = fmaf(av.y, bv.z, acc[1][2]);
            acc[1][3] = fmaf(av.y, bv.w, acc[1][3]);
            acc[2][0] = fmaf(av.z, bv.x, acc[2][0]);
            acc[2][1] = fmaf(av.z, bv.y, acc[2][1]);
            acc[2][2] = fmaf(av.z, bv.z, acc[2][2]);
            acc[2][3] = fmaf(av.z, bv.w, acc[2][3]);
            acc[3][0] = fmaf(av.w, bv.x, acc[3][0]);
            acc[3][1] = fmaf(av.w, bv.y, acc[3][1]);
            acc[3][2] = fmaf(av.w, bv.z, acc[3][2]);
            acc[3][3] = fmaf(av.w, bv.w, acc[3][3]);
        }
    }

#pragma unroll
    for (int i = 0; i < 4; ++i) {
        const int row = row0 + tmr * 4 + i;
        if (row < nsum) {
            float4 v = make_float4(acc[i][0], acc[i][1], acc[i][2], acc[i][3]);
            *reinterpret_cast<float4*>(&g_att[(size_t)row * NREL + tnc * 4]) = v;
        }
    }
}

// ---------------- Phase B: per-bag softmax chain ----------------
__global__ __launch_bounds__(NTB, 2)
void bag_softmax_kernel(const float* __restrict__ bias,
                        const int*   __restrict__ scope,
                        float*       __restrict__ out)
{
    __shared__ float attS[MAXM][BP];
    __shared__ float smS[MAXM][BP];
    __shared__ float biasS[NREL];

    const int b = blockIdx.x;
    const int t = threadIdx.x;

    const int start = scope[2 * b];
    int m = scope[2 * b + 1] - start;
    if (m > MAXM) m = MAXM;

    if (t >= 128 && t < 256) biasS[t - 128] = bias[t - 128];

    // load att rows for this bag (L2 scratch), coalesced vec4
    const int tot4 = m * (NREL / 4);
    for (int idx = t; idx < tot4; idx += NTB) {
        const int j   = idx >> 5;
        const int col = (idx & 31) * 4;
        *reinterpret_cast<float4*>(&attS[j][col]) =
            *reinterpret_cast<const float4*>(&g_att[(size_t)(start + j) * NREL + col]);
    }
    __syncthreads();

    // --- B1: column softmax over j -> smS[j][n], thread-per-n, no shuffles ---
    if (t < NREL) {
        const int n = t;
        float mx = -FLT_MAX;
        for (int j = 0; j < m; ++j) mx = fmaxf(mx, attS[j][n]);
        float ssum = 0.f;
        for (int j = 0; j < m; ++j) {
            const float e = __expf(attS[j][n] - mx);
            smS[j][n] = e;
            ssum += e;
        }
        const float inv = 1.f / ssum;
        for (int j = 0; j < m; ++j) smS[j][n] *= inv;
    }
    __syncthreads();

    // --- B2: full[n,k] = sum_j smS[j][n] * attS[j][k]  (register-tiled) ---
    // thread (tn = t>>4, tk = t&15) owns n in {4tn+64un+i}, k in {4tk+64uk+jv}
    const int tn = t >> 4;
    const int tk = t & 15;

    float fa[2][4][2][4];   // [un][i][uk][jv]
#pragma unroll
    for (int un = 0; un < 2; ++un)
#pragma unroll
        for (int i = 0; i < 4; ++i)
#pragma unroll
            for (int uk = 0; uk < 2; ++uk)
#pragma unroll
                for (int jv = 0; jv < 4; ++jv) fa[un][i][uk][jv] = 0.f;

#pragma unroll 2
    for (int j = 0; j < m; ++j) {
        const float4 s0 = *reinterpret_cast<const float4*>(&smS[j][tn * 4]);
        const float4 s1 = *reinterpret_cast<const float4*>(&smS[j][64 + tn * 4]);
        const float4 a0 = *reinterpret_cast<const float4*>(&attS[j][tk * 4]);
        const float4 a1 = *reinterpret_cast<const float4*>(&attS[j][64 + tk * 4]);
        const float sv[2][4] = {{s0.x, s0.y, s0.z, s0.w}, {s1.x, s1.y, s1.z, s1.w}};
        const float av[2][4] = {{a0.x, a0.y, a0.z, a0.w}, {a1.x, a1.y, a1.z, a1.w}};
#pragma unroll
        for (int un = 0; un < 2; ++un)
#pragma unroll
            for (int i = 0; i < 4; ++i)
#pragma unroll
                for (int uk = 0; uk < 2; ++uk)
#pragma unroll
                    for (int jv = 0; jv < 4; ++jv)
                        fa[un][i][uk][jv] = fmaf(sv[un][i], av[uk][jv], fa[un][i][uk][jv]);
    }

    // add bias
    const float4 bb0 = *reinterpret_cast<const float4*>(&biasS[tk * 4]);
    const float4 bb1 = *reinterpret_cast<const float4*>(&biasS[64 + tk * 4]);
    const float bv[2][4] = {{bb0.x, bb0.y, bb0.z, bb0.w}, {bb1.x, bb1.y, bb1.z, bb1.w}};
#pragma unroll
    for (int un = 0; un < 2; ++un)
#pragma unroll
        for (int i = 0; i < 4; ++i)
#pragma unroll
            for (int uk = 0; uk < 2; ++uk)
#pragma unroll
                for (int jv = 0; jv < 4; ++jv) fa[un][i][uk][jv] += bv[uk][jv];

    // --- B3: row softmax over k, emit diagonal ---
    // each row n lives on the 16 threads sharing tn (a half-warp: shfl_xor 1,2,4,8)
#pragma unroll
    for (int un = 0; un < 2; ++un) {
#pragma unroll
        for (int i = 0; i < 4; ++i) {
            float mx = -FLT_MAX;
#pragma unroll
            for (int uk = 0; uk < 2; ++uk)
#pragma unroll
                for (int jv = 0; jv < 4; ++jv) mx = fmaxf(mx, fa[un][i][uk][jv]);
#pragma unroll
            for (int o = 8; o; o >>= 1) mx = fmaxf(mx, __shfl_xor_sync(0xffffffffu, mx, o));
            float es = 0.f;
            float ev[2][4];
#pragma unroll
            for (int uk = 0; uk < 2; ++uk)
#pragma unroll
                for (int jv = 0; jv < 4; ++jv) {
                    ev[uk][jv] = __expf(fa[un][i][uk][jv] - mx);
                    es += ev[uk][jv];
                }
#pragma unroll
            for (int o = 8; o; o >>= 1) es += __shfl_xor_sync(0xffffffffu, es, o);
            if (tk == tn) {
                const int n = tn * 4 + 64 * un + i;   // diag: k==n -> uk==un, jv==i
                out[(size_t)b * NREL + n] = ev[un][i] / es;
            }
        }
    }
}

extern "C" void kernel_launch(void* const* d_in, const int* in_sizes, int n_in,
                              void* d_out, int out_size)
{
    (void)n_in; (void)out_size;
    const float* rep   = (const float*)d_in[0];
    const float* W     = (const float*)d_in[1];
    const float* bias  = (const float*)d_in[2];
    const int*   scope = (const int*)d_in[3];
    float* out = (float*)d_out;

    const int nsum = in_sizes[0] / D_DIM;
    const int B    = in_sizes[3] / 2;

    const int gridA = (nsum + BM - 1) / BM;
    gemm_att_kernel<<<gridA, NTA>>>(rep, W, nsum);
    bag_softmax_kernel<<<B, NTB>>>(bias, scope, out);
}